// round 16
// baseline (speedup 1.0000x reference)
#include <cuda_runtime.h>
#include <cuda_bf16.h>
#include <math.h>
#include <stdint.h>

#define BB 4096
#define DD 1024

#define THRESH   0.5f
#define MARGIN   0.1f
#define SCALE_P  2.0f
#define SCALE_N  40.0f
#define EPS      1e-5f

// Static scratch (no allocs).
__device__ float g_sim[(size_t)BB * BB];
__device__ __align__(16) __nv_bfloat16 g_xb[(size_t)BB * DD];
__device__ __align__(16) unsigned char g_lab8[BB];
__device__ float g_pmin[(size_t)BB * 32];
__device__ float g_pmax[(size_t)BB * 32];
__device__ float g_rowloss[BB];
__device__ int g_c1 = 0, g_c2 = 0, g_c3 = 0;

#define NPERS 296                   // 2 CTAs/SM x 148 SMs, all co-resident

// ---------------------------------------------------------------------------
// Helpers
// ---------------------------------------------------------------------------
__device__ __forceinline__ uint32_t smem_u32(const void* p) {
    uint32_t a;
    asm("{ .reg .u64 t; cvta.to.shared.u64 t, %1; cvt.u32.u64 %0, t; }"
        : "=r"(a) : "l"(p));
    return a;
}
#define CP_ASYNC16(dst, src) \
    asm volatile("cp.async.cg.shared.global [%0], [%1], 16;" :: "r"(dst), "l"(src))
#define CP_COMMIT() asm volatile("cp.async.commit_group;" ::: "memory")
#define CP_WAIT(n)  asm volatile("cp.async.wait_group %0;" :: "n"(n) : "memory")

__device__ __forceinline__ void ldmatrix_x4(uint32_t& r0, uint32_t& r1,
                                            uint32_t& r2, uint32_t& r3,
                                            uint32_t addr) {
    asm volatile("ldmatrix.sync.aligned.m8n8.x4.shared.b16 {%0,%1,%2,%3}, [%4];"
                 : "=r"(r0), "=r"(r1), "=r"(r2), "=r"(r3) : "r"(addr));
}
__device__ __forceinline__ void mma_bf16(float& c0, float& c1, float& c2, float& c3,
                                         uint32_t a0, uint32_t a1, uint32_t a2,
                                         uint32_t a3, uint32_t b0, uint32_t b1) {
    asm volatile(
        "mma.sync.aligned.m16n8k16.row.col.f32.bf16.bf16.f32 "
        "{%0,%1,%2,%3}, {%4,%5,%6,%7}, {%8,%9}, {%0,%1,%2,%3};"
        : "+f"(c0), "+f"(c1), "+f"(c2), "+f"(c3)
        : "r"(a0), "r"(a1), "r"(a2), "r"(a3), "r"(b0), "r"(b1));
}

// Grid-wide barrier for exactly-resident persistent grids.
__device__ __forceinline__ void gbar(int* ctr, int target) {
    __syncthreads();
    if (threadIdx.x == 0) {
        __threadfence();
        atomicAdd(ctr, 1);
        while (atomicAdd(ctr, 0) < target) __nanosleep(64);
        __threadfence();
    }
    __syncthreads();
}

// ---------------------------------------------------------------------------
// GEMM tile config (R15 proven).
// ---------------------------------------------------------------------------
#define KC 64
#define ROWB 144                    // 64*2 + 16 pad
#define TILE_B (128 * ROWB)         // 18432 B per A or B stage
#define OFF_B  (2 * TILE_B)
#define SMEM_DYN (4 * TILE_B)       // 73728 B
#define NT 32
#define NTILE (NT * (NT + 1) / 2)   // 528

__device__ __forceinline__ void do_tile(int t, char* smem, int tid) {
    int bi = (int)((65.0f - sqrtf(4225.0f - 8.0f * (float)t)) * 0.5f);
    while ((bi + 1) * (65 - (bi + 1)) / 2 <= t) bi++;
    while (bi * (65 - bi) / 2 > t) bi--;
    const int bj = bi + (t - bi * (65 - bi) / 2);

    __shared__ unsigned char labR[128], labC[128];
    const uint32_t sA = smem_u32(smem);
    const uint32_t sB = sA + OFF_B;

    const int wid = tid >> 5, lane = tid & 31;
    const int warp_m = wid >> 2;
    const int warp_n = wid & 3;
    const int row0 = bi * 128, col0 = bj * 128;

    if (tid < 128) labR[tid] = g_lab8[row0 + tid];
    else           labC[tid - 128] = g_lab8[col0 + tid - 128];

    uint32_t dstA[4];
    const __nv_bfloat16 *srcA[4], *srcB[4];
#pragma unroll
    for (int p = 0; p < 4; p++) {
        const int ii = p * 256 + tid;
        const int r = ii >> 3, kc = ii & 7;
        dstA[p] = (uint32_t)(r * ROWB + kc * 16);
        srcA[p] = g_xb + (size_t)(row0 + r) * DD + kc * 8;
        srcB[p] = g_xb + (size_t)(col0 + r) * DD + kc * 8;
    }

    float acc[4][4][4];
#pragma unroll
    for (int a = 0; a < 4; a++)
#pragma unroll
        for (int b = 0; b < 4; b++)
#pragma unroll
            for (int c = 0; c < 4; c++) acc[a][b][c] = 0.0f;

    const int a_mrow = warp_m * 64 + (lane & 7) + ((lane >> 3) & 1) * 8;
    const int a_kcol = (lane >> 4) << 3;
    const int b_nrow = warp_n * 32 + (lane & 7) + ((lane >> 4) << 3);
    const int b_kcol = ((lane >> 3) & 1) << 3;

#pragma unroll
    for (int p = 0; p < 4; p++) {
        CP_ASYNC16(sA + dstA[p], srcA[p]);
        CP_ASYNC16(sB + dstA[p], srcB[p]);
    }
    CP_COMMIT();

    for (int ck = 0; ck < DD / KC; ck++) {
        CP_WAIT(0);
        __syncthreads();

        if (ck + 1 < DD / KC) {
            const uint32_t st = ((ck + 1) & 1) * TILE_B;
            const int k0 = (ck + 1) * KC;
#pragma unroll
            for (int p = 0; p < 4; p++) {
                CP_ASYNC16(sA + st + dstA[p], srcA[p] + k0);
                CP_ASYNC16(sB + st + dstA[p], srcB[p] + k0);
            }
            CP_COMMIT();
        }

        const uint32_t stA = sA + (ck & 1) * TILE_B;
        const uint32_t stB = sB + (ck & 1) * TILE_B;

#pragma unroll
        for (int ks = 0; ks < KC / 16; ks++) {
            uint32_t af[4][4], bf[2][4];
#pragma unroll
            for (int mf = 0; mf < 4; mf++)
                ldmatrix_x4(af[mf][0], af[mf][1], af[mf][2], af[mf][3],
                            stA + (uint32_t)((a_mrow + mf * 16) * ROWB
                                             + (ks * 16 + a_kcol) * 2));
#pragma unroll
            for (int nfp = 0; nfp < 2; nfp++)
                ldmatrix_x4(bf[nfp][0], bf[nfp][1], bf[nfp][2], bf[nfp][3],
                            stB + (uint32_t)((b_nrow + nfp * 16) * ROWB
                                             + (ks * 16 + b_kcol) * 2));
#pragma unroll
            for (int mf = 0; mf < 4; mf++)
#pragma unroll
                for (int nf = 0; nf < 4; nf++) {
                    const uint32_t b0 = bf[nf >> 1][(nf & 1) * 2];
                    const uint32_t b1 = bf[nf >> 1][(nf & 1) * 2 + 1];
                    mma_bf16(acc[mf][nf][0], acc[mf][nf][1],
                             acc[mf][nf][2], acc[mf][nf][3],
                             af[mf][0], af[mf][1], af[mf][2], af[mf][3], b0, b1);
                }
        }
    }
    __syncthreads();

    // Epilogue: regs -> padded SMEM (stride 129).
    float* smf = (float*)smem;
    {
        const int r_lo = warp_m * 64 + (lane >> 2);
        const int c_lo = warp_n * 32 + (lane & 3) * 2;
#pragma unroll
        for (int mf = 0; mf < 4; mf++)
#pragma unroll
            for (int nf = 0; nf < 4; nf++) {
                const int r = r_lo + mf * 16;
                const int c = c_lo + nf * 8;
                smf[r * 129 + c]           = acc[mf][nf][0];
                smf[r * 129 + c + 1]       = acc[mf][nf][1];
                smf[(r + 8) * 129 + c]     = acc[mf][nf][2];
                smf[(r + 8) * 129 + c + 1] = acc[mf][nf][3];
            }
    }
    __syncthreads();

    const int cc = tid & 127;
    const int rh = tid >> 7;
#pragma unroll 4
    for (int i = 0; i < 64; i++) {
        const int r = i * 2 + rh;
        g_sim[(size_t)(row0 + r) * BB + col0 + cc] = smf[r * 129 + cc];
    }
    if (bi != bj) {
#pragma unroll 4
        for (int i = 0; i < 64; i++) {
            const int r = i * 2 + rh;
            g_sim[(size_t)(col0 + r) * BB + row0 + cc] = smf[cc * 129 + r];
        }
    }

    // Fused mining pass 1.
    if (tid < 128) {
        const int r = tid;
        const int gi = row0 + r;
        const unsigned char li = labR[r];
        float mp = INFINITY, mn = -INFINITY;
#pragma unroll 4
        for (int c = 0; c < 128; c++) {
            const float s = smf[r * 129 + c];
            if (labC[c] != li) {
                mn = fmaxf(mn, s);
            } else if (gi != col0 + c && s < 1.0f - EPS) {
                mp = fminf(mp, s);
            }
        }
        g_pmin[(size_t)gi * 32 + bj] = mp;
        g_pmax[(size_t)gi * 32 + bj] = mn;
    } else if (bi != bj) {
        const int j = tid - 128;
        const int gj = col0 + j;
        const unsigned char lj = labC[j];
        float mp = INFINITY, mn = -INFINITY;
#pragma unroll 4
        for (int rr = 0; rr < 128; rr++) {
            const float s = smf[rr * 129 + j];
            if (labR[rr] != lj) {
                mn = fmaxf(mn, s);
            } else if (gj != row0 + rr && s < 1.0f - EPS) {
                mp = fminf(mp, s);
            }
        }
        g_pmin[(size_t)gj * 32 + bi] = mp;
        g_pmax[(size_t)gj * 32 + bi] = mn;
    }
    __syncthreads();   // labR/labC + smf reuse safety for next tile
}

// ---------------------------------------------------------------------------
// Single persistent kernel: convert | barrier | GEMM tiles | barrier | rows.
// ---------------------------------------------------------------------------
__global__ __launch_bounds__(256, 2) void fused_all(
        float* __restrict__ out,
        const float4* __restrict__ x,
        const int* __restrict__ labels) {
    extern __shared__ __align__(16) char smem[];
    const int cta = blockIdx.x;
    const int tid = threadIdx.x;
    const int wid = tid >> 5, lane = tid & 31;

    // ---- Phase 0: convert x -> bf16, labels -> u8 ----
    for (int i = cta * 256 + tid; i < BB * DD / 8; i += NPERS * 256) {
        const float4 v0 = x[i * 2];
        const float4 v1 = x[i * 2 + 1];
        __nv_bfloat162 a = __floats2bfloat162_rn(v0.x, v0.y);
        __nv_bfloat162 b = __floats2bfloat162_rn(v0.z, v0.w);
        __nv_bfloat162 c = __floats2bfloat162_rn(v1.x, v1.y);
        __nv_bfloat162 d = __floats2bfloat162_rn(v1.z, v1.w);
        uint4 w;
        memcpy(&w.x, &a, 4); memcpy(&w.y, &b, 4);
        memcpy(&w.z, &c, 4); memcpy(&w.w, &d, 4);
        ((uint4*)g_xb)[i] = w;
    }
    if (cta == 0) {
#pragma unroll
        for (int k = 0; k < 4; k++) {
            int4 lv = *(const int4*)(labels + tid * 16 + k * 4);
            uchar4 u;
            u.x = (unsigned char)lv.x; u.y = (unsigned char)lv.y;
            u.z = (unsigned char)lv.z; u.w = (unsigned char)lv.w;
            *(uchar4*)(g_lab8 + tid * 16 + k * 4) = u;
        }
    }
    gbar(&g_c1, NPERS);

    // ---- Phase 1: GEMM tiles (static round-robin over 528) ----
    for (int t = cta; t < NTILE; t += NPERS) do_tile(t, smem, tid);
    gbar(&g_c2, NPERS);

    // ---- Phase 2: per-row mining sums ----
    __shared__ float wr0[8], wr1[8];
    __shared__ int   wri[8];
    __shared__ float s_mp, s_mn;
    __shared__ int   s_last;
    unsigned char* slab = (unsigned char*)smem;   // 4KB label cache
    *(uint4*)(slab + tid * 16) = ((const uint4*)g_lab8)[tid];
    __syncthreads();

    for (int r = cta; r < BB; r += NPERS) {
        if (wid == 0) {
            float mp = g_pmin[(size_t)r * 32 + lane];
            float mn = g_pmax[(size_t)r * 32 + lane];
#pragma unroll
            for (int o = 16; o > 0; o >>= 1) {
                mp = fminf(mp, __shfl_xor_sync(0xFFFFFFFFu, mp, o));
                mn = fmaxf(mn, __shfl_xor_sync(0xFFFFFFFFu, mn, o));
            }
            if (lane == 0) { s_mp = mp; s_mn = mn; }
        }
        __syncthreads();
        const float mp = s_mp, mn = s_mn;
        const unsigned char li = slab[r];

        const float* simrow = &g_sim[(size_t)r * BB];
        float psum = 0.0f, nsum = 0.0f;
        int flags = 0;
#pragma unroll
        for (int c = 0; c < 4; c++) {
            const int j0 = c * 1024 + tid * 4;
            const float4 v = __ldcs((const float4*)(simrow + j0));
            const uint32_t lw = *(const uint32_t*)(slab + j0);
            const float sv[4] = {v.x, v.y, v.z, v.w};
#pragma unroll
            for (int e = 0; e < 4; e++) {
                const int j = j0 + e;
                const float s = sv[e];
                if (((lw >> (e * 8)) & 255u) != li) {
                    if (s + MARGIN > mp) { nsum += __expf(SCALE_N * (s - THRESH)); flags |= 2; }
                } else if (j != r && s < 1.0f - EPS) {
                    if (s - MARGIN < mn) { psum += __expf(-SCALE_P * (s - THRESH)); flags |= 1; }
                }
            }
        }
#pragma unroll
        for (int o = 16; o > 0; o >>= 1) {
            psum += __shfl_xor_sync(0xFFFFFFFFu, psum, o);
            nsum += __shfl_xor_sync(0xFFFFFFFFu, nsum, o);
            flags |= __shfl_xor_sync(0xFFFFFFFFu, flags, o);
        }
        if (lane == 0) { wr0[wid] = psum; wr1[wid] = nsum; wri[wid] = flags; }
        __syncthreads();
        if (tid == 0) {
            float ps = wr0[0], ns = wr1[0];
            int fl = wri[0];
#pragma unroll
            for (int w = 1; w < 8; w++) { ps += wr0[w]; ns += wr1[w]; fl |= wri[w]; }
            const bool has_row = isfinite(mp) && (mn > -INFINITY) && (fl & 1) && (fl & 2);
            float loss = 0.0f;
            if (has_row) loss = log1pf(ps) / SCALE_P + log1pf(ns) / SCALE_N;
            g_rowloss[r] = loss;
        }
        __syncthreads();
    }

    // ---- Final: last CTA reduces row losses and resets counters ----
    if (tid == 0) {
        __threadfence();
        const int old = atomicAdd(&g_c3, 1);
        s_last = (old == NPERS - 1) ? 1 : 0;
    }
    __syncthreads();
    if (s_last) {
        __threadfence();
        float s = 0.0f;
        for (int k = tid; k < BB; k += 256) s += __ldcg(&g_rowloss[k]);
#pragma unroll
        for (int o = 16; o > 0; o >>= 1) s += __shfl_xor_sync(0xFFFFFFFFu, s, o);
        if (lane == 0) wr0[wid] = s;
        __syncthreads();
        if (tid == 0) {
            float t = 0.0f;
#pragma unroll
            for (int w = 0; w < 8; w++) t += wr0[w];
            out[0] = t / (float)BB;
            g_c1 = 0; g_c2 = 0; g_c3 = 0;   // reset for next graph replay
        }
    }
}

extern "C" void kernel_launch(void* const* d_in, const int* in_sizes, int n_in,
                              void* d_out, int out_size) {
    const float* x = (const float*)d_in[0];
    const int* labels = (const int*)d_in[1];
    float* out = (float*)d_out;

    cudaFuncSetAttribute(fused_all, cudaFuncAttributeMaxDynamicSharedMemorySize,
                         SMEM_DYN);
    fused_all<<<NPERS, 256, SMEM_DYN>>>(out, (const float4*)x, labels);
}